// round 7
// baseline (speedup 1.0000x reference)
#include <cuda_runtime.h>
#include <cstdint>

// PointNet_V3 fused, round 6 (= round 5 resubmit; R5 died to infra, not kernel):
//  - branch2 split into two 32-channel passes (recompute h) -> ~110 live regs,
//    launch_bounds(128,4) => 16 warps/SM
//  - launch order puts branch2 at index 3 so ncu (-s 5) captures it
//  - scan loads vectorized (int4)

#define CIN 16
#define C1  64
#define C2  128
#define SMAX 20000
#define NMAX 1100000
#define TPB 128

typedef unsigned long long ull;

// ---- persistent device scratch ----
__device__ __align__(16) float    g_W1f [CIN * C1];
__device__ __align__(16) float    g_b1f [C1];
__device__ __align__(16) ull      g_W1p [CIN * 32];   // packed (c, c+32) pairs
__device__ __align__(16) ull      g_b1p [32];
__device__ __align__(16) float    g_W2af[CIN * C2];
__device__ __align__(16) float    g_b2af[C2];
__device__ __align__(16) float    g_W2bf[C2 * C1];
__device__ __align__(16) float    g_b2bf[C1];
__device__ __align__(16) unsigned g_pmax[C1];
__device__ __align__(16) int      g_counts[SMAX + 16];
__device__ __align__(16) int      g_base  [SMAX + 1];
__device__ __align__(16) int      g_work  [SMAX + 1];
__device__ __align__(16) int      g_order [NMAX];

// ---- f32x2 helpers ----
__device__ __forceinline__ ull pack2(float x, float y) {
    ull r; asm("mov.b64 %0,{%1,%2};" : "=l"(r) : "f"(x), "f"(y)); return r;
}
__device__ __forceinline__ float2 unpack2(ull v) {
    float2 f; asm("mov.b64 {%0,%1},%2;" : "=f"(f.x), "=f"(f.y) : "l"(v)); return f;
}
__device__ __forceinline__ void fma2(ull& d, ull a, ull b) {
    asm("fma.rn.f32x2 %0,%1,%2,%0;" : "+l"(d) : "l"(a), "l"(b));
}
__device__ __forceinline__ ull relu2(ull v) {
    float2 f = unpack2(v);
    return pack2(fmaxf(f.x, 0.0f), fmaxf(f.y, 0.0f));
}

// ---- BN fold:  y = x*a + (b - m*a),  a = g/sqrt(v+eps) ----
__global__ void prep_kernel(const float* __restrict__ W1,  const float* __restrict__ g1,
                            const float* __restrict__ b1,  const float* __restrict__ m1,
                            const float* __restrict__ v1,
                            const float* __restrict__ W2a, const float* __restrict__ g2a,
                            const float* __restrict__ b2a, const float* __restrict__ m2a,
                            const float* __restrict__ v2a,
                            const float* __restrict__ W2b, const float* __restrict__ g2b,
                            const float* __restrict__ b2b, const float* __restrict__ m2b,
                            const float* __restrict__ v2b)
{
    __shared__ float a1[C1], a2a[C2], a2b[C1];
    int t = threadIdx.x;
    if (t < C1)  { float a = g1[t]  * rsqrtf(v1[t]  + 1e-3f); a1[t]  = a; g_b1f[t]  = b1[t]  - m1[t]  * a; }
    if (t < C2)  { float a = g2a[t] * rsqrtf(v2a[t] + 1e-3f); a2a[t] = a; g_b2af[t] = b2a[t] - m2a[t] * a; }
    if (t < C1)  { float a = g2b[t] * rsqrtf(v2b[t] + 1e-3f); a2b[t] = a; g_b2bf[t] = b2b[t] - m2b[t] * a; }
    __syncthreads();
    for (int i = t; i < CIN * C1; i += blockDim.x) g_W1f[i]  = W1[i]  * a1[i & (C1 - 1)];
    for (int i = t; i < CIN * C2; i += blockDim.x) g_W2af[i] = W2a[i] * a2a[i & (C2 - 1)];
    for (int i = t; i < C2 * C1;  i += blockDim.x) g_W2bf[i] = W2b[i] * a2b[i & (C1 - 1)];
    __syncthreads();
    if (t < 32) {
        for (int k = 0; k < CIN; k++)
            g_W1p[k * 32 + t] = pack2(g_W1f[k * C1 + t], g_W1f[k * C1 + t + 32]);
        g_b1p[t] = pack2(g_b1f[t], g_b1f[t + 32]);
    }
}

__global__ void zero_kernel(int S) {
    int i = blockIdx.x * blockDim.x + threadIdx.x;
    if (i < SMAX + 16) g_counts[i] = 0;
    if (i < C1) g_pmax[i] = 0u;
}

__global__ void hist_kernel(const int* __restrict__ seg, int N) {
    int i = blockIdx.x * blockDim.x + threadIdx.x;
    if (i < N) atomicAdd(&g_counts[seg[i]], 1);
}

// single block, 1024 threads; int4 loads + warp-shuffle scan
__global__ void scan_kernel(int S, int N) {
    __shared__ int wsum[32];
    int t = threadIdx.x;
    int chunk = (S + 1023) >> 10;
    chunk = (chunk + 3) & ~3;               // multiple of 4 for int4
    int lo = t * chunk;
    int sum = 0;
    const int4* c4 = (const int4*)g_counts;
    if (lo < S) {
        int hi4 = (min(lo + chunk, S) + 3) >> 2;
        for (int i = lo >> 2; i < hi4; i++) {
            int4 v = c4[i];
            sum += v.x + v.y + v.z + v.w;   // out-of-range entries are zero-padded
        }
    }

    int lane = t & 31, wid = t >> 5;
    int v = sum;
    #pragma unroll
    for (int d = 1; d < 32; d <<= 1) {
        int o = __shfl_up_sync(0xFFFFFFFFu, v, d);
        if (lane >= d) v += o;
    }
    if (lane == 31) wsum[wid] = v;
    __syncthreads();
    if (wid == 0) {
        int w = wsum[lane];
        #pragma unroll
        for (int d = 1; d < 32; d <<= 1) {
            int o = __shfl_up_sync(0xFFFFFFFFu, w, d);
            if (lane >= d) w += o;
        }
        wsum[lane] = w;
    }
    __syncthreads();
    int run = v - sum + (wid ? wsum[wid - 1] : 0);

    int hi = min(lo + chunk, S);
    for (int i = lo; i < hi; i++) {
        int c = g_counts[i];
        g_base[i] = run; g_work[i] = run;
        run += c;
    }
    if (t == 1023) g_base[S] = N;
}

__global__ void scatter_kernel(const int* __restrict__ seg, int N) {
    int i = blockIdx.x * blockDim.x + threadIdx.x;
    if (i < N) {
        int pos = atomicAdd(&g_work[seg[i]], 1);
        g_order[pos] = i;
    }
}

// ================= M2: branch2 + global max-pool =================
// smem: sW2b[8192] | sW2a[2048] | sb2a[128] | sb2b[64] | inbuf[TPB*17]
#define M2_SMEM (C2*C1 + CIN*C2 + C2 + C1 + TPB*17)

__global__ __launch_bounds__(TPB, 4) void branch2_kernel(const float* __restrict__ inp, int N)
{
    extern __shared__ float smem[];
    float* sW2b = smem;
    float* sW2a = sW2b + C2 * C1;
    float* sb2a = sW2a + CIN * C2;
    float* sb2b = sb2a + C2;
    float* inbf = sb2b + C1;

    const int tid = threadIdx.x;

    for (int i = tid; i < C2 * C1;  i += TPB) sW2b[i] = g_W2bf[i];
    for (int i = tid; i < CIN * C2; i += TPB) sW2a[i] = g_W2af[i];
    if (tid < C2) sb2a[tid] = g_b2af[tid];
    if (tid < C1) sb2b[tid] = g_b2bf[tid];

    {
        size_t base = (size_t)blockIdx.x * TPB * CIN;
        size_t total = (size_t)N * CIN;
        for (int i = tid; i < TPB * CIN; i += TPB) {
            size_t g = base + i;
            float v = (g < total) ? inp[g] : 0.0f;
            inbf[(i >> 4) * 17 + (i & 15)] = v;
        }
    }
    __syncthreads();

    const int p = blockIdx.x * TPB + tid;
    const bool active = (p < N);
    const float* myin = inbf + tid * 17;
    const unsigned lane = tid & 31;

    // two passes over output-channel halves: 16 acc ull each, h recomputed
    #pragma unroll 1
    for (int pass = 0; pass < 2; pass++) {
        const int cbase = pass * 32;
        ull acc[16];
        #pragma unroll
        for (int i = 0; i < 16; i++)
            acc[i] = pack2(sb2b[cbase + 2 * i], sb2b[cbase + 2 * i + 1]);

        #pragma unroll 1
        for (int q = 0; q < 4; q++) {
            // ---- h chunk: 32 channels in registers ----
            ull h[16];
            #pragma unroll
            for (int i = 0; i < 16; i++)
                h[i] = pack2(sb2a[q * 32 + 2 * i], sb2a[q * 32 + 2 * i + 1]);
            #pragma unroll
            for (int k = 0; k < CIN; k++) {
                ull ak = pack2(myin[k], myin[k]);
                const ulonglong2* w = (const ulonglong2*)(sW2a + k * C2 + q * 32);
                #pragma unroll
                for (int i = 0; i < 8; i++) {
                    ulonglong2 ww = w[i];
                    fma2(h[2 * i], ak, ww.x);
                    fma2(h[2 * i + 1], ak, ww.y);
                }
            }
            #pragma unroll
            for (int i = 0; i < 16; i++) h[i] = relu2(h[i]);

            // ---- consume h into this pass's 32 channels ----
            #pragma unroll
            for (int jj = 0; jj < 16; jj++) {
                float2 hp = unpack2(h[jj]);
                {
                    ull hh = pack2(hp.x, hp.x);
                    const ulonglong2* w = (const ulonglong2*)(sW2b + (q * 32 + 2 * jj) * C1 + cbase);
                    #pragma unroll
                    for (int i = 0; i < 8; i++) {
                        ulonglong2 ww = w[i];
                        fma2(acc[2 * i], hh, ww.x);
                        fma2(acc[2 * i + 1], hh, ww.y);
                    }
                }
                {
                    ull hh = pack2(hp.y, hp.y);
                    const ulonglong2* w = (const ulonglong2*)(sW2b + (q * 32 + 2 * jj + 1) * C1 + cbase);
                    #pragma unroll
                    for (int i = 0; i < 8; i++) {
                        ulonglong2 ww = w[i];
                        fma2(acc[2 * i], hh, ww.x);
                        fma2(acc[2 * i + 1], hh, ww.y);
                    }
                }
            }
        }

        // max-pool epilogue for this half
        #pragma unroll
        for (int i = 0; i < 16; i++) {
            float2 v = unpack2(acc[i]);
            float v0 = active ? fmaxf(v.x, 0.0f) : 0.0f;
            float v1 = active ? fmaxf(v.y, 0.0f) : 0.0f;
            unsigned m0 = __reduce_max_sync(0xFFFFFFFFu, __float_as_uint(v0));
            unsigned m1 = __reduce_max_sync(0xFFFFFFFFu, __float_as_uint(v1));
            if (lane == 0) {
                atomicMax(&g_pmax[cbase + 2 * i],     m0);
                atomicMax(&g_pmax[cbase + 2 * i + 1], m1);
            }
        }
    }
}

// ================= M1: warp-per-segment branch1 + reductions =================
#define M1_TPB 256
#define M1_WPB (M1_TPB / 32)

__global__ __launch_bounds__(M1_TPB) void segred_kernel(const float* __restrict__ inp,
                                                        float* __restrict__ out, int S)
{
    __shared__ ull sW[CIN * 32];
    __shared__ ull sB[32];
    int tid = threadIdx.x;
    for (int i = tid; i < CIN * 32; i += M1_TPB) sW[i] = g_W1p[i];
    if (tid < 32) sB[tid] = g_b1p[tid];
    __syncthreads();

    int s = blockIdx.x * M1_WPB + (tid >> 5);
    if (s >= S) return;
    int lane = tid & 31;

    ull w[CIN];
    #pragma unroll
    for (int k = 0; k < CIN; k++) w[k] = sW[k * 32 + lane];
    ull bias = sB[lane];

    int start = g_base[s], end = g_base[s + 1];
    float s0 = 0.0f, s1 = 0.0f, m0 = 0.0f, m1 = 0.0f;

    float vnext = 0.0f;
    if (start < end) {
        int p0 = g_order[start];
        vnext = __ldg(inp + (size_t)p0 * CIN + (lane & 15));
    }
    for (int i = start; i < end; i++) {
        float v = vnext;
        if (i + 1 < end) {
            int pn = g_order[i + 1];
            vnext = __ldg(inp + (size_t)pn * CIN + (lane & 15));
        }
        ull acc = bias;
        #pragma unroll
        for (int k = 0; k < CIN; k++) {
            float bk = __shfl_sync(0xFFFFFFFFu, v, k);
            fma2(acc, pack2(bk, bk), w[k]);
        }
        float2 x = unpack2(acc);
        float a0 = fmaxf(x.x, 0.0f), a1 = fmaxf(x.y, 0.0f);
        s0 += a0; s1 += a1;
        m0 = fmaxf(m0, a0); m1 = fmaxf(m1, a1);
    }

    float p0 = __uint_as_float(g_pmax[lane]);
    float p1 = __uint_as_float(g_pmax[lane + 32]);

    // channel shuffle groups=3: out[s, c*3 + {0:sum, 1:max, 2:pool}]
    float* o = out + (size_t)s * (3 * C1);
    o[lane * 3 + 0] = s0;
    o[lane * 3 + 1] = m0;
    o[lane * 3 + 2] = p0;
    o[(lane + 32) * 3 + 0] = s1;
    o[(lane + 32) * 3 + 1] = m1;
    o[(lane + 32) * 3 + 2] = p1;
}

extern "C" void kernel_launch(void* const* d_in, const int* in_sizes, int n_in,
                              void* d_out, int out_size)
{
    const float* inputs = (const float*)d_in[0];
    const int*   unq    = (const int*)  d_in[1];

    int base = (in_sizes[2] == 1) ? 3 : 2;
    const float* W1  = (const float*)d_in[base + 0];
    const float* g1  = (const float*)d_in[base + 1];
    const float* b1  = (const float*)d_in[base + 2];
    const float* m1  = (const float*)d_in[base + 3];
    const float* v1  = (const float*)d_in[base + 4];
    const float* W2a = (const float*)d_in[base + 5];
    const float* g2a = (const float*)d_in[base + 6];
    const float* b2a = (const float*)d_in[base + 7];
    const float* m2a = (const float*)d_in[base + 8];
    const float* v2a = (const float*)d_in[base + 9];
    const float* W2b = (const float*)d_in[base + 10];
    const float* g2b = (const float*)d_in[base + 11];
    const float* b2b = (const float*)d_in[base + 12];
    const float* m2b = (const float*)d_in[base + 13];
    const float* v2b = (const float*)d_in[base + 14];

    int N = in_sizes[0] / CIN;
    if (N > NMAX) N = NMAX;
    int S = out_size / (3 * C1);
    if (S > SMAX) S = SMAX;

    size_t m2_smem = M2_SMEM * sizeof(float);
    cudaFuncSetAttribute(branch2_kernel, cudaFuncAttributeMaxDynamicSharedMemorySize,
                         (int)m2_smem);

    prep_kernel<<<1, 256>>>(W1, g1, b1, m1, v1,
                            W2a, g2a, b2a, m2a, v2a,
                            W2b, g2b, b2b, m2b, v2b);
    zero_kernel<<<(SMAX + 256 + 16) / 256, 256>>>(S);
    hist_kernel<<<(N + 255) / 256, 256>>>(unq, N);
    branch2_kernel<<<(N + TPB - 1) / TPB, TPB, m2_smem>>>(inputs, N);   // idx 3: profiled
    scan_kernel<<<1, 1024>>>(S, N);
    scatter_kernel<<<(N + 255) / 256, 256>>>(unq, N);
    segred_kernel<<<(S + M1_WPB - 1) / M1_WPB, M1_TPB>>>(inputs, (float*)d_out, S);
}

// round 10
// speedup vs baseline: 4.0605x; 4.0605x over previous
#include <cuda_runtime.h>
#include <cuda_bf16.h>
#include <cstdint>

// PointNet_V3 fused, round 10 (= round 9 resubmit; R9 died to infra, not kernel):
// branch2 via warp-level mma.sync (bf16 split-3), in-register GEMM1->GEMM2
// fragment chaining, persistent CTAs. branch1 segment path unchanged.

#define CIN 16
#define C1  64
#define C2  128
#define SMAX 20000
#define NMAX 1100000

typedef unsigned long long ull;
typedef unsigned int u32;

// ---- persistent device scratch ----
__device__ __align__(16) float    g_W1f [CIN * C1];
__device__ __align__(16) float    g_b1f [C1];
__device__ __align__(16) ull      g_W1p [CIN * 32];
__device__ __align__(16) ull      g_b1p [32];
__device__ __align__(16) float    g_W2af[CIN * C2];
__device__ __align__(16) float    g_b2af[C2];
__device__ __align__(16) float    g_W2bf[C2 * C1];
__device__ __align__(16) float    g_b2bf[C1];
__device__ __align__(16) uint4    g_fragA[16 * 32];      // GEMM1 B-fragments
__device__ __align__(16) uint4    g_fragB[64 * 32];      // GEMM2 B-fragments
__device__ __align__(16) unsigned g_pmax[C1];
__device__ __align__(16) int      g_counts[SMAX + 16];
__device__ __align__(16) int      g_base  [SMAX + 1];
__device__ __align__(16) int      g_work  [SMAX + 1];
__device__ __align__(16) int      g_order [NMAX];

// ---- f32x2 helpers (segred) ----
__device__ __forceinline__ ull pack2(float x, float y) {
    ull r; asm("mov.b64 %0,{%1,%2};" : "=l"(r) : "f"(x), "f"(y)); return r;
}
__device__ __forceinline__ float2 unpack2(ull v) {
    float2 f; asm("mov.b64 {%0,%1},%2;" : "=f"(f.x), "=f"(f.y) : "l"(v)); return f;
}
__device__ __forceinline__ void fma2(ull& d, ull a, ull b) {
    asm("fma.rn.f32x2 %0,%1,%2,%0;" : "+l"(d) : "l"(a), "l"(b));
}

// ---- bf16 split helpers ----
__device__ __forceinline__ u32 bf2_bits(__nv_bfloat162 h) {
    u32 r; __builtin_memcpy(&r, &h, 4); return r;
}
__device__ __forceinline__ void split2(float x0, float x1, u32& hi, u32& lo) {
    __nv_bfloat162 h = __floats2bfloat162_rn(x0, x1);
    hi = bf2_bits(h);
    float2 hf = __bfloat1622float2(h);
    __nv_bfloat162 l = __floats2bfloat162_rn(x0 - hf.x, x1 - hf.y);
    lo = bf2_bits(l);
}

// warp mma: D += A(m16k16,row) * B(k16n8,col), bf16 in, f32 acc
__device__ __forceinline__ void mma16816(float* d, const u32* a, u32 b0, u32 b1) {
    asm volatile(
        "mma.sync.aligned.m16n8k16.row.col.f32.bf16.bf16.f32 "
        "{%0,%1,%2,%3},{%4,%5,%6,%7},{%8,%9},{%0,%1,%2,%3};"
        : "+f"(d[0]), "+f"(d[1]), "+f"(d[2]), "+f"(d[3])
        : "r"(a[0]), "r"(a[1]), "r"(a[2]), "r"(a[3]), "r"(b0), "r"(b1));
}

// ================= prep: BN fold + mma weight fragments =================
__global__ void prep_kernel(const float* __restrict__ W1,  const float* __restrict__ g1,
                            const float* __restrict__ b1,  const float* __restrict__ m1,
                            const float* __restrict__ v1,
                            const float* __restrict__ W2a, const float* __restrict__ g2a,
                            const float* __restrict__ b2a, const float* __restrict__ m2a,
                            const float* __restrict__ v2a,
                            const float* __restrict__ W2b, const float* __restrict__ g2b,
                            const float* __restrict__ b2b, const float* __restrict__ m2b,
                            const float* __restrict__ v2b)
{
    __shared__ float a1[C1], a2a[C2], a2b[C1];
    int t = threadIdx.x;
    if (t < C1)  { float a = g1[t]  * rsqrtf(v1[t]  + 1e-3f); a1[t]  = a; g_b1f[t]  = b1[t]  - m1[t]  * a; }
    if (t < C2)  { float a = g2a[t] * rsqrtf(v2a[t] + 1e-3f); a2a[t] = a; g_b2af[t] = b2a[t] - m2a[t] * a; }
    if (t < C1)  { float a = g2b[t] * rsqrtf(v2b[t] + 1e-3f); a2b[t] = a; g_b2bf[t] = b2b[t] - m2b[t] * a; }
    __syncthreads();
    for (int i = t; i < CIN * C1; i += blockDim.x) g_W1f[i]  = W1[i]  * a1[i & (C1 - 1)];
    for (int i = t; i < CIN * C2; i += blockDim.x) g_W2af[i] = W2a[i] * a2a[i & (C2 - 1)];
    for (int i = t; i < C2 * C1;  i += blockDim.x) g_W2bf[i] = W2b[i] * a2b[i & (C1 - 1)];
    __syncthreads();
    if (t < 32) {
        for (int k = 0; k < CIN; k++)
            g_W1p[k * 32 + t] = pack2(g_W1f[k * C1 + t], g_W1f[k * C1 + t + 32]);
        g_b1p[t] = pack2(g_b1f[t], g_b1f[t + 32]);
    }
    // GEMM1 B-fragments: Wa[n][k] = g_W2af[k*C2+n]; tile j covers n = 8j+g
    for (int idx = t; idx < 16 * 32; idx += blockDim.x) {
        int j = idx >> 5, lane = idx & 31;
        int g = lane >> 2, tg = lane & 3;
        int n = 8 * j + g, k0 = 2 * tg;
        float v00 = g_W2af[(k0    ) * C2 + n], v01 = g_W2af[(k0 + 1) * C2 + n];
        float v10 = g_W2af[(k0 + 8) * C2 + n], v11 = g_W2af[(k0 + 9) * C2 + n];
        u32 h0, l0, h1, l1;
        split2(v00, v01, h0, l0);
        split2(v10, v11, h1, l1);
        g_fragA[idx] = make_uint4(h0, h1, l0, l1);
    }
    // GEMM2 B-fragments: Wb[n][k] = g_W2bf[k*C1+n]; (s,j): n = 8j+g, k0 = 16s+2tg
    for (int idx = t; idx < 64 * 32; idx += blockDim.x) {
        int sj = idx >> 5, lane = idx & 31;
        int s = sj >> 3, j = sj & 7;
        int g = lane >> 2, tg = lane & 3;
        int n = 8 * j + g, k0 = 16 * s + 2 * tg;
        float v00 = g_W2bf[(k0    ) * C1 + n], v01 = g_W2bf[(k0 + 1) * C1 + n];
        float v10 = g_W2bf[(k0 + 8) * C1 + n], v11 = g_W2bf[(k0 + 9) * C1 + n];
        u32 h0, l0, h1, l1;
        split2(v00, v01, h0, l0);
        split2(v10, v11, h1, l1);
        g_fragB[idx] = make_uint4(h0, h1, l0, l1);
    }
}

__global__ void zero_kernel(int S) {
    int i = blockIdx.x * blockDim.x + threadIdx.x;
    if (i < SMAX + 16) g_counts[i] = 0;
    if (i < C1) g_pmax[i] = 0u;
}

__global__ void hist_kernel(const int* __restrict__ seg, int N) {
    int i = blockIdx.x * blockDim.x + threadIdx.x;
    if (i < N) atomicAdd(&g_counts[seg[i]], 1);
}

__global__ void scan_kernel(int S, int N) {
    __shared__ int wsum[32];
    int t = threadIdx.x;
    int chunk = (S + 1023) >> 10;
    chunk = (chunk + 3) & ~3;
    int lo = t * chunk;
    int sum = 0;
    const int4* c4 = (const int4*)g_counts;
    if (lo < S) {
        int hi4 = (min(lo + chunk, S) + 3) >> 2;
        for (int i = lo >> 2; i < hi4; i++) {
            int4 v = c4[i];
            sum += v.x + v.y + v.z + v.w;
        }
    }
    int lane = t & 31, wid = t >> 5;
    int v = sum;
    #pragma unroll
    for (int d = 1; d < 32; d <<= 1) {
        int o = __shfl_up_sync(0xFFFFFFFFu, v, d);
        if (lane >= d) v += o;
    }
    if (lane == 31) wsum[wid] = v;
    __syncthreads();
    if (wid == 0) {
        int w = wsum[lane];
        #pragma unroll
        for (int d = 1; d < 32; d <<= 1) {
            int o = __shfl_up_sync(0xFFFFFFFFu, w, d);
            if (lane >= d) w += o;
        }
        wsum[lane] = w;
    }
    __syncthreads();
    int run = v - sum + (wid ? wsum[wid - 1] : 0);
    int hi = min(lo + chunk, S);
    for (int i = lo; i < hi; i++) {
        int c = g_counts[i];
        g_base[i] = run; g_work[i] = run;
        run += c;
    }
    if (t == 1023) g_base[S] = N;
}

__global__ void scatter_kernel(const int* __restrict__ seg, int N) {
    int i = blockIdx.x * blockDim.x + threadIdx.x;
    if (i < N) {
        int pos = atomicAdd(&g_work[seg[i]], 1);
        g_order[pos] = i;
    }
}

// ================= branch2 via mma.sync =================
// per warp: one m16 tile (16 points). 240 HMMA per tile.
__global__ __launch_bounds__(128) void branch2_mma(const float* __restrict__ inp,
                                                   int N, int NT16)
{
    __shared__ uint4 sFragA[16 * 32];
    __shared__ uint4 sFragB[64 * 32];
    __shared__ float sB2a[C2];
    __shared__ float sB2b[C1];
    __shared__ u32   spool[C1];

    const int tid = threadIdx.x;
    const int wid = tid >> 5;
    const int lane = tid & 31;
    const int g  = lane >> 2;
    const int tg = lane & 3;

    for (int i = tid; i < 16 * 32; i += 128) sFragA[i] = g_fragA[i];
    for (int i = tid; i < 64 * 32; i += 128) sFragB[i] = g_fragB[i];
    if (tid < C2) sB2a[tid] = g_b2af[tid];
    if (tid < C1) { sB2b[tid] = g_b2bf[tid]; spool[tid] = 0u; }
    __syncthreads();

    float runmax[16];
    #pragma unroll
    for (int i = 0; i < 16; i++) runmax[i] = 0.0f;

    const int wstride = gridDim.x * 4;

    for (int wt = blockIdx.x * 4 + wid; wt < NT16; wt += wstride) {
        const int tb = wt * 16;
        const int p0 = tb + g;
        const int p1 = tb + g + 8;
        const bool act0 = (p0 < N);
        const bool act1 = (p1 < N);

        // ---- A fragments: X rows g, g+8; cols 2tg.., 2tg+8.. (hi/lo split) ----
        float2 z2 = make_float2(0.0f, 0.0f);
        const float* rp0 = inp + (size_t)p0 * CIN + 2 * tg;
        const float* rp1 = inp + (size_t)p1 * CIN + 2 * tg;
        float2 xa = act0 ? *(const float2*)(rp0)     : z2;
        float2 xc = act0 ? *(const float2*)(rp0 + 8) : z2;
        float2 xb = act1 ? *(const float2*)(rp1)     : z2;
        float2 xd = act1 ? *(const float2*)(rp1 + 8) : z2;
        u32 Ahi[4], Alo[4];
        split2(xa.x, xa.y, Ahi[0], Alo[0]);
        split2(xb.x, xb.y, Ahi[1], Alo[1]);
        split2(xc.x, xc.y, Ahi[2], Alo[2]);
        split2(xd.x, xd.y, Ahi[3], Alo[3]);

        // ---- GEMM1 (K=16) + bias/relu + re-split -> H fragments ----
        u32 Hhi[8][4], Hlo[8][4];
        #pragma unroll
        for (int s = 0; s < 8; s++) {
            #pragma unroll
            for (int half = 0; half < 2; half++) {
                int j = 2 * s + half;
                float c[4] = {0.0f, 0.0f, 0.0f, 0.0f};
                uint4 f = sFragA[j * 32 + lane];
                mma16816(c, Ahi, f.x, f.y);
                mma16816(c, Ahi, f.z, f.w);
                mma16816(c, Alo, f.x, f.y);
                float2 bb = *(const float2*)(sB2a + 8 * j + 2 * tg);
                float v0 = fmaxf(c[0] + bb.x, 0.0f);
                float v1 = fmaxf(c[1] + bb.y, 0.0f);
                float v2 = fmaxf(c[2] + bb.x, 0.0f);
                float v3 = fmaxf(c[3] + bb.y, 0.0f);
                split2(v0, v1, Hhi[s][2 * half],     Hlo[s][2 * half]);
                split2(v2, v3, Hhi[s][2 * half + 1], Hlo[s][2 * half + 1]);
            }
        }

        // ---- GEMM2 (K=128 = 8 k-steps) ----
        float acc[8][4];
        #pragma unroll
        for (int j = 0; j < 8; j++)
            #pragma unroll
            for (int i = 0; i < 4; i++) acc[j][i] = 0.0f;
        #pragma unroll
        for (int s = 0; s < 8; s++) {
            #pragma unroll
            for (int j = 0; j < 8; j++) {
                uint4 f = sFragB[(s * 8 + j) * 32 + lane];
                mma16816(acc[j], Hhi[s], f.x, f.y);
                mma16816(acc[j], Hhi[s], f.z, f.w);
                mma16816(acc[j], Hlo[s], f.x, f.y);
            }
        }

        // ---- epilogue: bias + masked running max ----
        #pragma unroll
        for (int j = 0; j < 8; j++) {
            float2 bb = *(const float2*)(sB2b + 8 * j + 2 * tg);
            float v0 = acc[j][0] + bb.x, v1 = acc[j][1] + bb.y;   // row g
            float v2 = acc[j][2] + bb.x, v3 = acc[j][3] + bb.y;   // row g+8
            if (!act0) { v0 = 0.0f; v1 = 0.0f; }
            if (!act1) { v2 = 0.0f; v3 = 0.0f; }
            runmax[2 * j]     = fmaxf(runmax[2 * j],     fmaxf(v0, v2));
            runmax[2 * j + 1] = fmaxf(runmax[2 * j + 1], fmaxf(v1, v3));
        }
    }

    // ---- pool: smem reduce then 64 global atomics per CTA ----
    #pragma unroll
    for (int i = 0; i < 16; i++) {
        int col = 8 * (i >> 1) + 2 * tg + (i & 1);
        float v = fmaxf(runmax[i], 0.0f);
        atomicMax(&spool[col], __float_as_uint(v));
    }
    __syncthreads();
    if (tid < C1) atomicMax(&g_pmax[tid], spool[tid]);
}

// ================= branch1: warp-per-segment recompute + reductions =================
#define M1_TPB 256
#define M1_WPB (M1_TPB / 32)

__global__ __launch_bounds__(M1_TPB) void segred_kernel(const float* __restrict__ inp,
                                                        float* __restrict__ out, int S)
{
    __shared__ ull sW[CIN * 32];
    __shared__ ull sB[32];
    int tid = threadIdx.x;
    for (int i = tid; i < CIN * 32; i += M1_TPB) sW[i] = g_W1p[i];
    if (tid < 32) sB[tid] = g_b1p[tid];
    __syncthreads();

    int s = blockIdx.x * M1_WPB + (tid >> 5);
    if (s >= S) return;
    int lane = tid & 31;

    ull w[CIN];
    #pragma unroll
    for (int k = 0; k < CIN; k++) w[k] = sW[k * 32 + lane];
    ull bias = sB[lane];

    int start = g_base[s], end = g_base[s + 1];
    float s0 = 0.0f, s1 = 0.0f, m0 = 0.0f, m1 = 0.0f;

    float vnext = 0.0f;
    if (start < end) {
        int p0 = g_order[start];
        vnext = __ldg(inp + (size_t)p0 * CIN + (lane & 15));
    }
    for (int i = start; i < end; i++) {
        float v = vnext;
        if (i + 1 < end) {
            int pn = g_order[i + 1];
            vnext = __ldg(inp + (size_t)pn * CIN + (lane & 15));
        }
        ull acc = bias;
        #pragma unroll
        for (int k = 0; k < CIN; k++) {
            float bk = __shfl_sync(0xFFFFFFFFu, v, k);
            fma2(acc, pack2(bk, bk), w[k]);
        }
        float2 x = unpack2(acc);
        float a0 = fmaxf(x.x, 0.0f), a1 = fmaxf(x.y, 0.0f);
        s0 += a0; s1 += a1;
        m0 = fmaxf(m0, a0); m1 = fmaxf(m1, a1);
    }

    float p0 = __uint_as_float(g_pmax[lane]);
    float p1 = __uint_as_float(g_pmax[lane + 32]);

    float* o = out + (size_t)s * (3 * C1);
    o[lane * 3 + 0] = s0;
    o[lane * 3 + 1] = m0;
    o[lane * 3 + 2] = p0;
    o[(lane + 32) * 3 + 0] = s1;
    o[(lane + 32) * 3 + 1] = m1;
    o[(lane + 32) * 3 + 2] = p1;
}

extern "C" void kernel_launch(void* const* d_in, const int* in_sizes, int n_in,
                              void* d_out, int out_size)
{
    const float* inputs = (const float*)d_in[0];
    const int*   unq    = (const int*)  d_in[1];

    int base = (in_sizes[2] == 1) ? 3 : 2;
    const float* W1  = (const float*)d_in[base + 0];
    const float* g1  = (const float*)d_in[base + 1];
    const float* b1  = (const float*)d_in[base + 2];
    const float* m1  = (const float*)d_in[base + 3];
    const float* v1  = (const float*)d_in[base + 4];
    const float* W2a = (const float*)d_in[base + 5];
    const float* g2a = (const float*)d_in[base + 6];
    const float* b2a = (const float*)d_in[base + 7];
    const float* m2a = (const float*)d_in[base + 8];
    const float* v2a = (const float*)d_in[base + 9];
    const float* W2b = (const float*)d_in[base + 10];
    const float* g2b = (const float*)d_in[base + 11];
    const float* b2b = (const float*)d_in[base + 12];
    const float* m2b = (const float*)d_in[base + 13];
    const float* v2b = (const float*)d_in[base + 14];

    int N = in_sizes[0] / CIN;
    if (N > NMAX) N = NMAX;
    int S = out_size / (3 * C1);
    if (S > SMAX) S = SMAX;

    int NT16 = (N + 15) / 16;
    int grid2 = 592;
    if (grid2 * 4 > NT16) grid2 = (NT16 + 3) / 4;

    prep_kernel<<<1, 256>>>(W1, g1, b1, m1, v1,
                            W2a, g2a, b2a, m2a, v2a,
                            W2b, g2b, b2b, m2b, v2b);
    zero_kernel<<<(SMAX + 256 + 16) / 256, 256>>>(S);
    hist_kernel<<<(N + 255) / 256, 256>>>(unq, N);
    branch2_mma<<<grid2, 128>>>(inputs, N, NT16);             // idx 3: profiled
    scan_kernel<<<1, 1024>>>(S, N);
    scatter_kernel<<<(N + 255) / 256, 256>>>(unq, N);
    segred_kernel<<<(S + M1_WPB - 1) / M1_WPB, M1_TPB>>>(inputs, (float*)d_out, S);
}

// round 11
// speedup vs baseline: 4.1049x; 1.0109x over previous
#include <cuda_runtime.h>
#include <cuda_bf16.h>
#include <cstdint>

// PointNet_V3 fused, round 10 (= round 9 resubmit; R9 died to infra, not kernel):
// branch2 via warp-level mma.sync (bf16 split-3), in-register GEMM1->GEMM2
// fragment chaining, persistent CTAs. branch1 segment path unchanged.

#define CIN 16
#define C1  64
#define C2  128
#define SMAX 20000
#define NMAX 1100000

typedef unsigned long long ull;
typedef unsigned int u32;

// ---- persistent device scratch ----
__device__ __align__(16) float    g_W1f [CIN * C1];
__device__ __align__(16) float    g_b1f [C1];
__device__ __align__(16) ull      g_W1p [CIN * 32];
__device__ __align__(16) ull      g_b1p [32];
__device__ __align__(16) float    g_W2af[CIN * C2];
__device__ __align__(16) float    g_b2af[C2];
__device__ __align__(16) float    g_W2bf[C2 * C1];
__device__ __align__(16) float    g_b2bf[C1];
__device__ __align__(16) uint4    g_fragA[16 * 32];      // GEMM1 B-fragments
__device__ __align__(16) uint4    g_fragB[64 * 32];      // GEMM2 B-fragments
__device__ __align__(16) unsigned g_pmax[C1];
__device__ __align__(16) int      g_counts[SMAX + 16];
__device__ __align__(16) int      g_base  [SMAX + 1];
__device__ __align__(16) int      g_work  [SMAX + 1];
__device__ __align__(16) int      g_order [NMAX];

// ---- f32x2 helpers (segred) ----
__device__ __forceinline__ ull pack2(float x, float y) {
    ull r; asm("mov.b64 %0,{%1,%2};" : "=l"(r) : "f"(x), "f"(y)); return r;
}
__device__ __forceinline__ float2 unpack2(ull v) {
    float2 f; asm("mov.b64 {%0,%1},%2;" : "=f"(f.x), "=f"(f.y) : "l"(v)); return f;
}
__device__ __forceinline__ void fma2(ull& d, ull a, ull b) {
    asm("fma.rn.f32x2 %0,%1,%2,%0;" : "+l"(d) : "l"(a), "l"(b));
}

// ---- bf16 split helpers ----
__device__ __forceinline__ u32 bf2_bits(__nv_bfloat162 h) {
    u32 r; __builtin_memcpy(&r, &h, 4); return r;
}
__device__ __forceinline__ void split2(float x0, float x1, u32& hi, u32& lo) {
    __nv_bfloat162 h = __floats2bfloat162_rn(x0, x1);
    hi = bf2_bits(h);
    float2 hf = __bfloat1622float2(h);
    __nv_bfloat162 l = __floats2bfloat162_rn(x0 - hf.x, x1 - hf.y);
    lo = bf2_bits(l);
}

// warp mma: D += A(m16k16,row) * B(k16n8,col), bf16 in, f32 acc
__device__ __forceinline__ void mma16816(float* d, const u32* a, u32 b0, u32 b1) {
    asm volatile(
        "mma.sync.aligned.m16n8k16.row.col.f32.bf16.bf16.f32 "
        "{%0,%1,%2,%3},{%4,%5,%6,%7},{%8,%9},{%0,%1,%2,%3};"
        : "+f"(d[0]), "+f"(d[1]), "+f"(d[2]), "+f"(d[3])
        : "r"(a[0]), "r"(a[1]), "r"(a[2]), "r"(a[3]), "r"(b0), "r"(b1));
}

// ================= prep: BN fold + mma weight fragments =================
__global__ void prep_kernel(const float* __restrict__ W1,  const float* __restrict__ g1,
                            const float* __restrict__ b1,  const float* __restrict__ m1,
                            const float* __restrict__ v1,
                            const float* __restrict__ W2a, const float* __restrict__ g2a,
                            const float* __restrict__ b2a, const float* __restrict__ m2a,
                            const float* __restrict__ v2a,
                            const float* __restrict__ W2b, const float* __restrict__ g2b,
                            const float* __restrict__ b2b, const float* __restrict__ m2b,
                            const float* __restrict__ v2b)
{
    __shared__ float a1[C1], a2a[C2], a2b[C1];
    int t = threadIdx.x;
    if (t < C1)  { float a = g1[t]  * rsqrtf(v1[t]  + 1e-3f); a1[t]  = a; g_b1f[t]  = b1[t]  - m1[t]  * a; }
    if (t < C2)  { float a = g2a[t] * rsqrtf(v2a[t] + 1e-3f); a2a[t] = a; g_b2af[t] = b2a[t] - m2a[t] * a; }
    if (t < C1)  { float a = g2b[t] * rsqrtf(v2b[t] + 1e-3f); a2b[t] = a; g_b2bf[t] = b2b[t] - m2b[t] * a; }
    __syncthreads();
    for (int i = t; i < CIN * C1; i += blockDim.x) g_W1f[i]  = W1[i]  * a1[i & (C1 - 1)];
    for (int i = t; i < CIN * C2; i += blockDim.x) g_W2af[i] = W2a[i] * a2a[i & (C2 - 1)];
    for (int i = t; i < C2 * C1;  i += blockDim.x) g_W2bf[i] = W2b[i] * a2b[i & (C1 - 1)];
    __syncthreads();
    if (t < 32) {
        for (int k = 0; k < CIN; k++)
            g_W1p[k * 32 + t] = pack2(g_W1f[k * C1 + t], g_W1f[k * C1 + t + 32]);
        g_b1p[t] = pack2(g_b1f[t], g_b1f[t + 32]);
    }
    // GEMM1 B-fragments: Wa[n][k] = g_W2af[k*C2+n]; tile j covers n = 8j+g
    for (int idx = t; idx < 16 * 32; idx += blockDim.x) {
        int j = idx >> 5, lane = idx & 31;
        int g = lane >> 2, tg = lane & 3;
        int n = 8 * j + g, k0 = 2 * tg;
        float v00 = g_W2af[(k0    ) * C2 + n], v01 = g_W2af[(k0 + 1) * C2 + n];
        float v10 = g_W2af[(k0 + 8) * C2 + n], v11 = g_W2af[(k0 + 9) * C2 + n];
        u32 h0, l0, h1, l1;
        split2(v00, v01, h0, l0);
        split2(v10, v11, h1, l1);
        g_fragA[idx] = make_uint4(h0, h1, l0, l1);
    }
    // GEMM2 B-fragments: Wb[n][k] = g_W2bf[k*C1+n]; (s,j): n = 8j+g, k0 = 16s+2tg
    for (int idx = t; idx < 64 * 32; idx += blockDim.x) {
        int sj = idx >> 5, lane = idx & 31;
        int s = sj >> 3, j = sj & 7;
        int g = lane >> 2, tg = lane & 3;
        int n = 8 * j + g, k0 = 16 * s + 2 * tg;
        float v00 = g_W2bf[(k0    ) * C1 + n], v01 = g_W2bf[(k0 + 1) * C1 + n];
        float v10 = g_W2bf[(k0 + 8) * C1 + n], v11 = g_W2bf[(k0 + 9) * C1 + n];
        u32 h0, l0, h1, l1;
        split2(v00, v01, h0, l0);
        split2(v10, v11, h1, l1);
        g_fragB[idx] = make_uint4(h0, h1, l0, l1);
    }
}

__global__ void zero_kernel(int S) {
    int i = blockIdx.x * blockDim.x + threadIdx.x;
    if (i < SMAX + 16) g_counts[i] = 0;
    if (i < C1) g_pmax[i] = 0u;
}

__global__ void hist_kernel(const int* __restrict__ seg, int N) {
    int i = blockIdx.x * blockDim.x + threadIdx.x;
    if (i < N) atomicAdd(&g_counts[seg[i]], 1);
}

__global__ void scan_kernel(int S, int N) {
    __shared__ int wsum[32];
    int t = threadIdx.x;
    int chunk = (S + 1023) >> 10;
    chunk = (chunk + 3) & ~3;
    int lo = t * chunk;
    int sum = 0;
    const int4* c4 = (const int4*)g_counts;
    if (lo < S) {
        int hi4 = (min(lo + chunk, S) + 3) >> 2;
        for (int i = lo >> 2; i < hi4; i++) {
            int4 v = c4[i];
            sum += v.x + v.y + v.z + v.w;
        }
    }
    int lane = t & 31, wid = t >> 5;
    int v = sum;
    #pragma unroll
    for (int d = 1; d < 32; d <<= 1) {
        int o = __shfl_up_sync(0xFFFFFFFFu, v, d);
        if (lane >= d) v += o;
    }
    if (lane == 31) wsum[wid] = v;
    __syncthreads();
    if (wid == 0) {
        int w = wsum[lane];
        #pragma unroll
        for (int d = 1; d < 32; d <<= 1) {
            int o = __shfl_up_sync(0xFFFFFFFFu, w, d);
            if (lane >= d) w += o;
        }
        wsum[lane] = w;
    }
    __syncthreads();
    int run = v - sum + (wid ? wsum[wid - 1] : 0);
    int hi = min(lo + chunk, S);
    for (int i = lo; i < hi; i++) {
        int c = g_counts[i];
        g_base[i] = run; g_work[i] = run;
        run += c;
    }
    if (t == 1023) g_base[S] = N;
}

__global__ void scatter_kernel(const int* __restrict__ seg, int N) {
    int i = blockIdx.x * blockDim.x + threadIdx.x;
    if (i < N) {
        int pos = atomicAdd(&g_work[seg[i]], 1);
        g_order[pos] = i;
    }
}

// ================= branch2 via mma.sync =================
// per warp: one m16 tile (16 points). 240 HMMA per tile.
__global__ __launch_bounds__(128) void branch2_mma(const float* __restrict__ inp,
                                                   int N, int NT16)
{
    __shared__ uint4 sFragA[16 * 32];
    __shared__ uint4 sFragB[64 * 32];
    __shared__ float sB2a[C2];
    __shared__ float sB2b[C1];
    __shared__ u32   spool[C1];

    const int tid = threadIdx.x;
    const int wid = tid >> 5;
    const int lane = tid & 31;
    const int g  = lane >> 2;
    const int tg = lane & 3;

    for (int i = tid; i < 16 * 32; i += 128) sFragA[i] = g_fragA[i];
    for (int i = tid; i < 64 * 32; i += 128) sFragB[i] = g_fragB[i];
    if (tid < C2) sB2a[tid] = g_b2af[tid];
    if (tid < C1) { sB2b[tid] = g_b2bf[tid]; spool[tid] = 0u; }
    __syncthreads();

    float runmax[16];
    #pragma unroll
    for (int i = 0; i < 16; i++) runmax[i] = 0.0f;

    const int wstride = gridDim.x * 4;

    for (int wt = blockIdx.x * 4 + wid; wt < NT16; wt += wstride) {
        const int tb = wt * 16;
        const int p0 = tb + g;
        const int p1 = tb + g + 8;
        const bool act0 = (p0 < N);
        const bool act1 = (p1 < N);

        // ---- A fragments: X rows g, g+8; cols 2tg.., 2tg+8.. (hi/lo split) ----
        float2 z2 = make_float2(0.0f, 0.0f);
        const float* rp0 = inp + (size_t)p0 * CIN + 2 * tg;
        const float* rp1 = inp + (size_t)p1 * CIN + 2 * tg;
        float2 xa = act0 ? *(const float2*)(rp0)     : z2;
        float2 xc = act0 ? *(const float2*)(rp0 + 8) : z2;
        float2 xb = act1 ? *(const float2*)(rp1)     : z2;
        float2 xd = act1 ? *(const float2*)(rp1 + 8) : z2;
        u32 Ahi[4], Alo[4];
        split2(xa.x, xa.y, Ahi[0], Alo[0]);
        split2(xb.x, xb.y, Ahi[1], Alo[1]);
        split2(xc.x, xc.y, Ahi[2], Alo[2]);
        split2(xd.x, xd.y, Ahi[3], Alo[3]);

        // ---- GEMM1 (K=16) + bias/relu + re-split -> H fragments ----
        u32 Hhi[8][4], Hlo[8][4];
        #pragma unroll
        for (int s = 0; s < 8; s++) {
            #pragma unroll
            for (int half = 0; half < 2; half++) {
                int j = 2 * s + half;
                float c[4] = {0.0f, 0.0f, 0.0f, 0.0f};
                uint4 f = sFragA[j * 32 + lane];
                mma16816(c, Ahi, f.x, f.y);
                mma16816(c, Ahi, f.z, f.w);
                mma16816(c, Alo, f.x, f.y);
                float2 bb = *(const float2*)(sB2a + 8 * j + 2 * tg);
                float v0 = fmaxf(c[0] + bb.x, 0.0f);
                float v1 = fmaxf(c[1] + bb.y, 0.0f);
                float v2 = fmaxf(c[2] + bb.x, 0.0f);
                float v3 = fmaxf(c[3] + bb.y, 0.0f);
                split2(v0, v1, Hhi[s][2 * half],     Hlo[s][2 * half]);
                split2(v2, v3, Hhi[s][2 * half + 1], Hlo[s][2 * half + 1]);
            }
        }

        // ---- GEMM2 (K=128 = 8 k-steps) ----
        float acc[8][4];
        #pragma unroll
        for (int j = 0; j < 8; j++)
            #pragma unroll
            for (int i = 0; i < 4; i++) acc[j][i] = 0.0f;
        #pragma unroll
        for (int s = 0; s < 8; s++) {
            #pragma unroll
            for (int j = 0; j < 8; j++) {
                uint4 f = sFragB[(s * 8 + j) * 32 + lane];
                mma16816(acc[j], Hhi[s], f.x, f.y);
                mma16816(acc[j], Hhi[s], f.z, f.w);
                mma16816(acc[j], Hlo[s], f.x, f.y);
            }
        }

        // ---- epilogue: bias + masked running max ----
        #pragma unroll
        for (int j = 0; j < 8; j++) {
            float2 bb = *(const float2*)(sB2b + 8 * j + 2 * tg);
            float v0 = acc[j][0] + bb.x, v1 = acc[j][1] + bb.y;   // row g
            float v2 = acc[j][2] + bb.x, v3 = acc[j][3] + bb.y;   // row g+8
            if (!act0) { v0 = 0.0f; v1 = 0.0f; }
            if (!act1) { v2 = 0.0f; v3 = 0.0f; }
            runmax[2 * j]     = fmaxf(runmax[2 * j],     fmaxf(v0, v2));
            runmax[2 * j + 1] = fmaxf(runmax[2 * j + 1], fmaxf(v1, v3));
        }
    }

    // ---- pool: smem reduce then 64 global atomics per CTA ----
    #pragma unroll
    for (int i = 0; i < 16; i++) {
        int col = 8 * (i >> 1) + 2 * tg + (i & 1);
        float v = fmaxf(runmax[i], 0.0f);
        atomicMax(&spool[col], __float_as_uint(v));
    }
    __syncthreads();
    if (tid < C1) atomicMax(&g_pmax[tid], spool[tid]);
}

// ================= branch1: warp-per-segment recompute + reductions =================
#define M1_TPB 256
#define M1_WPB (M1_TPB / 32)

__global__ __launch_bounds__(M1_TPB) void segred_kernel(const float* __restrict__ inp,
                                                        float* __restrict__ out, int S)
{
    __shared__ ull sW[CIN * 32];
    __shared__ ull sB[32];
    int tid = threadIdx.x;
    for (int i = tid; i < CIN * 32; i += M1_TPB) sW[i] = g_W1p[i];
    if (tid < 32) sB[tid] = g_b1p[tid];
    __syncthreads();

    int s = blockIdx.x * M1_WPB + (tid >> 5);
    if (s >= S) return;
    int lane = tid & 31;

    ull w[CIN];
    #pragma unroll
    for (int k = 0; k < CIN; k++) w[k] = sW[k * 32 + lane];
    ull bias = sB[lane];

    int start = g_base[s], end = g_base[s + 1];
    float s0 = 0.0f, s1 = 0.0f, m0 = 0.0f, m1 = 0.0f;

    float vnext = 0.0f;
    if (start < end) {
        int p0 = g_order[start];
        vnext = __ldg(inp + (size_t)p0 * CIN + (lane & 15));
    }
    for (int i = start; i < end; i++) {
        float v = vnext;
        if (i + 1 < end) {
            int pn = g_order[i + 1];
            vnext = __ldg(inp + (size_t)pn * CIN + (lane & 15));
        }
        ull acc = bias;
        #pragma unroll
        for (int k = 0; k < CIN; k++) {
            float bk = __shfl_sync(0xFFFFFFFFu, v, k);
            fma2(acc, pack2(bk, bk), w[k]);
        }
        float2 x = unpack2(acc);
        float a0 = fmaxf(x.x, 0.0f), a1 = fmaxf(x.y, 0.0f);
        s0 += a0; s1 += a1;
        m0 = fmaxf(m0, a0); m1 = fmaxf(m1, a1);
    }

    float p0 = __uint_as_float(g_pmax[lane]);
    float p1 = __uint_as_float(g_pmax[lane + 32]);

    float* o = out + (size_t)s * (3 * C1);
    o[lane * 3 + 0] = s0;
    o[lane * 3 + 1] = m0;
    o[lane * 3 + 2] = p0;
    o[(lane + 32) * 3 + 0] = s1;
    o[(lane + 32) * 3 + 1] = m1;
    o[(lane + 32) * 3 + 2] = p1;
}

extern "C" void kernel_launch(void* const* d_in, const int* in_sizes, int n_in,
                              void* d_out, int out_size)
{
    const float* inputs = (const float*)d_in[0];
    const int*   unq    = (const int*)  d_in[1];

    int base = (in_sizes[2] == 1) ? 3 : 2;
    const float* W1  = (const float*)d_in[base + 0];
    const float* g1  = (const float*)d_in[base + 1];
    const float* b1  = (const float*)d_in[base + 2];
    const float* m1  = (const float*)d_in[base + 3];
    const float* v1  = (const float*)d_in[base + 4];
    const float* W2a = (const float*)d_in[base + 5];
    const float* g2a = (const float*)d_in[base + 6];
    const float* b2a = (const float*)d_in[base + 7];
    const float* m2a = (const float*)d_in[base + 8];
    const float* v2a = (const float*)d_in[base + 9];
    const float* W2b = (const float*)d_in[base + 10];
    const float* g2b = (const float*)d_in[base + 11];
    const float* b2b = (const float*)d_in[base + 12];
    const float* m2b = (const float*)d_in[base + 13];
    const float* v2b = (const float*)d_in[base + 14];

    int N = in_sizes[0] / CIN;
    if (N > NMAX) N = NMAX;
    int S = out_size / (3 * C1);
    if (S > SMAX) S = SMAX;

    int NT16 = (N + 15) / 16;
    int grid2 = 592;
    if (grid2 * 4 > NT16) grid2 = (NT16 + 3) / 4;

    prep_kernel<<<1, 256>>>(W1, g1, b1, m1, v1,
                            W2a, g2a, b2a, m2a, v2a,
                            W2b, g2b, b2b, m2b, v2b);
    zero_kernel<<<(SMAX + 256 + 16) / 256, 256>>>(S);
    hist_kernel<<<(N + 255) / 256, 256>>>(unq, N);
    branch2_mma<<<grid2, 128>>>(inputs, N, NT16);             // idx 3: profiled
    scan_kernel<<<1, 1024>>>(S, N);
    scatter_kernel<<<(N + 255) / 256, 256>>>(unq, N);
    segred_kernel<<<(S + M1_WPB - 1) / M1_WPB, M1_TPB>>>(inputs, (float*)d_out, S);
}

// round 12
// speedup vs baseline: 4.1572x; 1.0127x over previous
#include <cuda_runtime.h>
#include <cuda_bf16.h>
#include <cstdint>

// PointNet_V3 fused, round 10 (= round 9 resubmit; R9 died to infra, not kernel):
// branch2 via warp-level mma.sync (bf16 split-3), in-register GEMM1->GEMM2
// fragment chaining, persistent CTAs. branch1 segment path unchanged.

#define CIN 16
#define C1  64
#define C2  128
#define SMAX 20000
#define NMAX 1100000

typedef unsigned long long ull;
typedef unsigned int u32;

// ---- persistent device scratch ----
__device__ __align__(16) float    g_W1f [CIN * C1];
__device__ __align__(16) float    g_b1f [C1];
__device__ __align__(16) ull      g_W1p [CIN * 32];
__device__ __align__(16) ull      g_b1p [32];
__device__ __align__(16) float    g_W2af[CIN * C2];
__device__ __align__(16) float    g_b2af[C2];
__device__ __align__(16) float    g_W2bf[C2 * C1];
__device__ __align__(16) float    g_b2bf[C1];
__device__ __align__(16) uint4    g_fragA[16 * 32];      // GEMM1 B-fragments
__device__ __align__(16) uint4    g_fragB[64 * 32];      // GEMM2 B-fragments
__device__ __align__(16) unsigned g_pmax[C1];
__device__ __align__(16) int      g_counts[SMAX + 16];
__device__ __align__(16) int      g_base  [SMAX + 1];
__device__ __align__(16) int      g_work  [SMAX + 1];
__device__ __align__(16) int      g_order [NMAX];

// ---- f32x2 helpers (segred) ----
__device__ __forceinline__ ull pack2(float x, float y) {
    ull r; asm("mov.b64 %0,{%1,%2};" : "=l"(r) : "f"(x), "f"(y)); return r;
}
__device__ __forceinline__ float2 unpack2(ull v) {
    float2 f; asm("mov.b64 {%0,%1},%2;" : "=f"(f.x), "=f"(f.y) : "l"(v)); return f;
}
__device__ __forceinline__ void fma2(ull& d, ull a, ull b) {
    asm("fma.rn.f32x2 %0,%1,%2,%0;" : "+l"(d) : "l"(a), "l"(b));
}

// ---- bf16 split helpers ----
__device__ __forceinline__ u32 bf2_bits(__nv_bfloat162 h) {
    u32 r; __builtin_memcpy(&r, &h, 4); return r;
}
__device__ __forceinline__ void split2(float x0, float x1, u32& hi, u32& lo) {
    __nv_bfloat162 h = __floats2bfloat162_rn(x0, x1);
    hi = bf2_bits(h);
    float2 hf = __bfloat1622float2(h);
    __nv_bfloat162 l = __floats2bfloat162_rn(x0 - hf.x, x1 - hf.y);
    lo = bf2_bits(l);
}

// warp mma: D += A(m16k16,row) * B(k16n8,col), bf16 in, f32 acc
__device__ __forceinline__ void mma16816(float* d, const u32* a, u32 b0, u32 b1) {
    asm volatile(
        "mma.sync.aligned.m16n8k16.row.col.f32.bf16.bf16.f32 "
        "{%0,%1,%2,%3},{%4,%5,%6,%7},{%8,%9},{%0,%1,%2,%3};"
        : "+f"(d[0]), "+f"(d[1]), "+f"(d[2]), "+f"(d[3])
        : "r"(a[0]), "r"(a[1]), "r"(a[2]), "r"(a[3]), "r"(b0), "r"(b1));
}

// ================= prep: BN fold + mma weight fragments =================
__global__ void prep_kernel(const float* __restrict__ W1,  const float* __restrict__ g1,
                            const float* __restrict__ b1,  const float* __restrict__ m1,
                            const float* __restrict__ v1,
                            const float* __restrict__ W2a, const float* __restrict__ g2a,
                            const float* __restrict__ b2a, const float* __restrict__ m2a,
                            const float* __restrict__ v2a,
                            const float* __restrict__ W2b, const float* __restrict__ g2b,
                            const float* __restrict__ b2b, const float* __restrict__ m2b,
                            const float* __restrict__ v2b)
{
    __shared__ float a1[C1], a2a[C2], a2b[C1];
    int t = threadIdx.x;
    if (t < C1)  { float a = g1[t]  * rsqrtf(v1[t]  + 1e-3f); a1[t]  = a; g_b1f[t]  = b1[t]  - m1[t]  * a; }
    if (t < C2)  { float a = g2a[t] * rsqrtf(v2a[t] + 1e-3f); a2a[t] = a; g_b2af[t] = b2a[t] - m2a[t] * a; }
    if (t < C1)  { float a = g2b[t] * rsqrtf(v2b[t] + 1e-3f); a2b[t] = a; g_b2bf[t] = b2b[t] - m2b[t] * a; }
    __syncthreads();
    for (int i = t; i < CIN * C1; i += blockDim.x) g_W1f[i]  = W1[i]  * a1[i & (C1 - 1)];
    for (int i = t; i < CIN * C2; i += blockDim.x) g_W2af[i] = W2a[i] * a2a[i & (C2 - 1)];
    for (int i = t; i < C2 * C1;  i += blockDim.x) g_W2bf[i] = W2b[i] * a2b[i & (C1 - 1)];
    __syncthreads();
    if (t < 32) {
        for (int k = 0; k < CIN; k++)
            g_W1p[k * 32 + t] = pack2(g_W1f[k * C1 + t], g_W1f[k * C1 + t + 32]);
        g_b1p[t] = pack2(g_b1f[t], g_b1f[t + 32]);
    }
    // GEMM1 B-fragments: Wa[n][k] = g_W2af[k*C2+n]; tile j covers n = 8j+g
    for (int idx = t; idx < 16 * 32; idx += blockDim.x) {
        int j = idx >> 5, lane = idx & 31;
        int g = lane >> 2, tg = lane & 3;
        int n = 8 * j + g, k0 = 2 * tg;
        float v00 = g_W2af[(k0    ) * C2 + n], v01 = g_W2af[(k0 + 1) * C2 + n];
        float v10 = g_W2af[(k0 + 8) * C2 + n], v11 = g_W2af[(k0 + 9) * C2 + n];
        u32 h0, l0, h1, l1;
        split2(v00, v01, h0, l0);
        split2(v10, v11, h1, l1);
        g_fragA[idx] = make_uint4(h0, h1, l0, l1);
    }
    // GEMM2 B-fragments: Wb[n][k] = g_W2bf[k*C1+n]; (s,j): n = 8j+g, k0 = 16s+2tg
    for (int idx = t; idx < 64 * 32; idx += blockDim.x) {
        int sj = idx >> 5, lane = idx & 31;
        int s = sj >> 3, j = sj & 7;
        int g = lane >> 2, tg = lane & 3;
        int n = 8 * j + g, k0 = 16 * s + 2 * tg;
        float v00 = g_W2bf[(k0    ) * C1 + n], v01 = g_W2bf[(k0 + 1) * C1 + n];
        float v10 = g_W2bf[(k0 + 8) * C1 + n], v11 = g_W2bf[(k0 + 9) * C1 + n];
        u32 h0, l0, h1, l1;
        split2(v00, v01, h0, l0);
        split2(v10, v11, h1, l1);
        g_fragB[idx] = make_uint4(h0, h1, l0, l1);
    }
}

__global__ void zero_kernel(int S) {
    int i = blockIdx.x * blockDim.x + threadIdx.x;
    if (i < SMAX + 16) g_counts[i] = 0;
    if (i < C1) g_pmax[i] = 0u;
}

__global__ void hist_kernel(const int* __restrict__ seg, int N) {
    int i = blockIdx.x * blockDim.x + threadIdx.x;
    if (i < N) atomicAdd(&g_counts[seg[i]], 1);
}

__global__ void scan_kernel(int S, int N) {
    __shared__ int wsum[32];
    int t = threadIdx.x;
    int chunk = (S + 1023) >> 10;
    chunk = (chunk + 3) & ~3;
    int lo = t * chunk;
    int sum = 0;
    const int4* c4 = (const int4*)g_counts;
    if (lo < S) {
        int hi4 = (min(lo + chunk, S) + 3) >> 2;
        for (int i = lo >> 2; i < hi4; i++) {
            int4 v = c4[i];
            sum += v.x + v.y + v.z + v.w;
        }
    }
    int lane = t & 31, wid = t >> 5;
    int v = sum;
    #pragma unroll
    for (int d = 1; d < 32; d <<= 1) {
        int o = __shfl_up_sync(0xFFFFFFFFu, v, d);
        if (lane >= d) v += o;
    }
    if (lane == 31) wsum[wid] = v;
    __syncthreads();
    if (wid == 0) {
        int w = wsum[lane];
        #pragma unroll
        for (int d = 1; d < 32; d <<= 1) {
            int o = __shfl_up_sync(0xFFFFFFFFu, w, d);
            if (lane >= d) w += o;
        }
        wsum[lane] = w;
    }
    __syncthreads();
    int run = v - sum + (wid ? wsum[wid - 1] : 0);
    int hi = min(lo + chunk, S);
    for (int i = lo; i < hi; i++) {
        int c = g_counts[i];
        g_base[i] = run; g_work[i] = run;
        run += c;
    }
    if (t == 1023) g_base[S] = N;
}

__global__ void scatter_kernel(const int* __restrict__ seg, int N) {
    int i = blockIdx.x * blockDim.x + threadIdx.x;
    if (i < N) {
        int pos = atomicAdd(&g_work[seg[i]], 1);
        g_order[pos] = i;
    }
}

// ================= branch2 via mma.sync =================
// per warp: one m16 tile (16 points). 240 HMMA per tile.
__global__ __launch_bounds__(128) void branch2_mma(const float* __restrict__ inp,
                                                   int N, int NT16)
{
    __shared__ uint4 sFragA[16 * 32];
    __shared__ uint4 sFragB[64 * 32];
    __shared__ float sB2a[C2];
    __shared__ float sB2b[C1];
    __shared__ u32   spool[C1];

    const int tid = threadIdx.x;
    const int wid = tid >> 5;
    const int lane = tid & 31;
    const int g  = lane >> 2;
    const int tg = lane & 3;

    for (int i = tid; i < 16 * 32; i += 128) sFragA[i] = g_fragA[i];
    for (int i = tid; i < 64 * 32; i += 128) sFragB[i] = g_fragB[i];
    if (tid < C2) sB2a[tid] = g_b2af[tid];
    if (tid < C1) { sB2b[tid] = g_b2bf[tid]; spool[tid] = 0u; }
    __syncthreads();

    float runmax[16];
    #pragma unroll
    for (int i = 0; i < 16; i++) runmax[i] = 0.0f;

    const int wstride = gridDim.x * 4;

    for (int wt = blockIdx.x * 4 + wid; wt < NT16; wt += wstride) {
        const int tb = wt * 16;
        const int p0 = tb + g;
        const int p1 = tb + g + 8;
        const bool act0 = (p0 < N);
        const bool act1 = (p1 < N);

        // ---- A fragments: X rows g, g+8; cols 2tg.., 2tg+8.. (hi/lo split) ----
        float2 z2 = make_float2(0.0f, 0.0f);
        const float* rp0 = inp + (size_t)p0 * CIN + 2 * tg;
        const float* rp1 = inp + (size_t)p1 * CIN + 2 * tg;
        float2 xa = act0 ? *(const float2*)(rp0)     : z2;
        float2 xc = act0 ? *(const float2*)(rp0 + 8) : z2;
        float2 xb = act1 ? *(const float2*)(rp1)     : z2;
        float2 xd = act1 ? *(const float2*)(rp1 + 8) : z2;
        u32 Ahi[4], Alo[4];
        split2(xa.x, xa.y, Ahi[0], Alo[0]);
        split2(xb.x, xb.y, Ahi[1], Alo[1]);
        split2(xc.x, xc.y, Ahi[2], Alo[2]);
        split2(xd.x, xd.y, Ahi[3], Alo[3]);

        // ---- GEMM1 (K=16) + bias/relu + re-split -> H fragments ----
        u32 Hhi[8][4], Hlo[8][4];
        #pragma unroll
        for (int s = 0; s < 8; s++) {
            #pragma unroll
            for (int half = 0; half < 2; half++) {
                int j = 2 * s + half;
                float c[4] = {0.0f, 0.0f, 0.0f, 0.0f};
                uint4 f = sFragA[j * 32 + lane];
                mma16816(c, Ahi, f.x, f.y);
                mma16816(c, Ahi, f.z, f.w);
                mma16816(c, Alo, f.x, f.y);
                float2 bb = *(const float2*)(sB2a + 8 * j + 2 * tg);
                float v0 = fmaxf(c[0] + bb.x, 0.0f);
                float v1 = fmaxf(c[1] + bb.y, 0.0f);
                float v2 = fmaxf(c[2] + bb.x, 0.0f);
                float v3 = fmaxf(c[3] + bb.y, 0.0f);
                split2(v0, v1, Hhi[s][2 * half],     Hlo[s][2 * half]);
                split2(v2, v3, Hhi[s][2 * half + 1], Hlo[s][2 * half + 1]);
            }
        }

        // ---- GEMM2 (K=128 = 8 k-steps) ----
        float acc[8][4];
        #pragma unroll
        for (int j = 0; j < 8; j++)
            #pragma unroll
            for (int i = 0; i < 4; i++) acc[j][i] = 0.0f;
        #pragma unroll
        for (int s = 0; s < 8; s++) {
            #pragma unroll
            for (int j = 0; j < 8; j++) {
                uint4 f = sFragB[(s * 8 + j) * 32 + lane];
                mma16816(acc[j], Hhi[s], f.x, f.y);
                mma16816(acc[j], Hhi[s], f.z, f.w);
                mma16816(acc[j], Hlo[s], f.x, f.y);
            }
        }

        // ---- epilogue: bias + masked running max ----
        #pragma unroll
        for (int j = 0; j < 8; j++) {
            float2 bb = *(const float2*)(sB2b + 8 * j + 2 * tg);
            float v0 = acc[j][0] + bb.x, v1 = acc[j][1] + bb.y;   // row g
            float v2 = acc[j][2] + bb.x, v3 = acc[j][3] + bb.y;   // row g+8
            if (!act0) { v0 = 0.0f; v1 = 0.0f; }
            if (!act1) { v2 = 0.0f; v3 = 0.0f; }
            runmax[2 * j]     = fmaxf(runmax[2 * j],     fmaxf(v0, v2));
            runmax[2 * j + 1] = fmaxf(runmax[2 * j + 1], fmaxf(v1, v3));
        }
    }

    // ---- pool: smem reduce then 64 global atomics per CTA ----
    #pragma unroll
    for (int i = 0; i < 16; i++) {
        int col = 8 * (i >> 1) + 2 * tg + (i & 1);
        float v = fmaxf(runmax[i], 0.0f);
        atomicMax(&spool[col], __float_as_uint(v));
    }
    __syncthreads();
    if (tid < C1) atomicMax(&g_pmax[tid], spool[tid]);
}

// ================= branch1: warp-per-segment recompute + reductions =================
#define M1_TPB 256
#define M1_WPB (M1_TPB / 32)

__global__ __launch_bounds__(M1_TPB) void segred_kernel(const float* __restrict__ inp,
                                                        float* __restrict__ out, int S)
{
    __shared__ ull sW[CIN * 32];
    __shared__ ull sB[32];
    int tid = threadIdx.x;
    for (int i = tid; i < CIN * 32; i += M1_TPB) sW[i] = g_W1p[i];
    if (tid < 32) sB[tid] = g_b1p[tid];
    __syncthreads();

    int s = blockIdx.x * M1_WPB + (tid >> 5);
    if (s >= S) return;
    int lane = tid & 31;

    ull w[CIN];
    #pragma unroll
    for (int k = 0; k < CIN; k++) w[k] = sW[k * 32 + lane];
    ull bias = sB[lane];

    int start = g_base[s], end = g_base[s + 1];
    float s0 = 0.0f, s1 = 0.0f, m0 = 0.0f, m1 = 0.0f;

    float vnext = 0.0f;
    if (start < end) {
        int p0 = g_order[start];
        vnext = __ldg(inp + (size_t)p0 * CIN + (lane & 15));
    }
    for (int i = start; i < end; i++) {
        float v = vnext;
        if (i + 1 < end) {
            int pn = g_order[i + 1];
            vnext = __ldg(inp + (size_t)pn * CIN + (lane & 15));
        }
        ull acc = bias;
        #pragma unroll
        for (int k = 0; k < CIN; k++) {
            float bk = __shfl_sync(0xFFFFFFFFu, v, k);
            fma2(acc, pack2(bk, bk), w[k]);
        }
        float2 x = unpack2(acc);
        float a0 = fmaxf(x.x, 0.0f), a1 = fmaxf(x.y, 0.0f);
        s0 += a0; s1 += a1;
        m0 = fmaxf(m0, a0); m1 = fmaxf(m1, a1);
    }

    float p0 = __uint_as_float(g_pmax[lane]);
    float p1 = __uint_as_float(g_pmax[lane + 32]);

    float* o = out + (size_t)s * (3 * C1);
    o[lane * 3 + 0] = s0;
    o[lane * 3 + 1] = m0;
    o[lane * 3 + 2] = p0;
    o[(lane + 32) * 3 + 0] = s1;
    o[(lane + 32) * 3 + 1] = m1;
    o[(lane + 32) * 3 + 2] = p1;
}

extern "C" void kernel_launch(void* const* d_in, const int* in_sizes, int n_in,
                              void* d_out, int out_size)
{
    const float* inputs = (const float*)d_in[0];
    const int*   unq    = (const int*)  d_in[1];

    int base = (in_sizes[2] == 1) ? 3 : 2;
    const float* W1  = (const float*)d_in[base + 0];
    const float* g1  = (const float*)d_in[base + 1];
    const float* b1  = (const float*)d_in[base + 2];
    const float* m1  = (const float*)d_in[base + 3];
    const float* v1  = (const float*)d_in[base + 4];
    const float* W2a = (const float*)d_in[base + 5];
    const float* g2a = (const float*)d_in[base + 6];
    const float* b2a = (const float*)d_in[base + 7];
    const float* m2a = (const float*)d_in[base + 8];
    const float* v2a = (const float*)d_in[base + 9];
    const float* W2b = (const float*)d_in[base + 10];
    const float* g2b = (const float*)d_in[base + 11];
    const float* b2b = (const float*)d_in[base + 12];
    const float* m2b = (const float*)d_in[base + 13];
    const float* v2b = (const float*)d_in[base + 14];

    int N = in_sizes[0] / CIN;
    if (N > NMAX) N = NMAX;
    int S = out_size / (3 * C1);
    if (S > SMAX) S = SMAX;

    int NT16 = (N + 15) / 16;
    int grid2 = 592;
    if (grid2 * 4 > NT16) grid2 = (NT16 + 3) / 4;

    prep_kernel<<<1, 256>>>(W1, g1, b1, m1, v1,
                            W2a, g2a, b2a, m2a, v2a,
                            W2b, g2b, b2b, m2b, v2b);
    zero_kernel<<<(SMAX + 256 + 16) / 256, 256>>>(S);
    hist_kernel<<<(N + 255) / 256, 256>>>(unq, N);
    branch2_mma<<<grid2, 128>>>(inputs, N, NT16);             // idx 3: profiled
    scan_kernel<<<1, 1024>>>(S, N);
    scatter_kernel<<<(N + 255) / 256, 256>>>(unq, N);
    segred_kernel<<<(S + M1_WPB - 1) / M1_WPB, M1_TPB>>>(inputs, (float*)d_out, S);
}